// round 17
// baseline (speedup 1.0000x reference)
#include <cuda_runtime.h>
#include <stdint.h>

// Problem constants
#define NB       64
#define NH       512
#define NW       512
#define NC       3
#define NUM_MASK 3072          // masked patches per image

// ---------------------------------------------------------------------------
// FINAL kernel — converged optimum for RandomMasking on GB300 (sm_103a).
// Best measured total 47.616 us (reproduced 4x; kernel ~43.4-44.1 us,
// DRAM ~67-69% = ~5.8 TB/s effective on the minimal 252 MB of traffic:
// 201 MB dense output writes + 50 MB reads for the 25% kept patches +
// L2-resident index slices).
//
// Grid (NPH=64 patch-rows, NB=64 images); block = 384 threads.
// Grid order (x=patch-row, y=image) is load-bearing: co-resident blocks
// cover consecutive bands of few images -> clustered DRAM streams, and the
// per-image 12 KB index slice is reused from L2 by 64 consecutive blocks.
// (Transposed order measured 54.2 us, DRAM 54.7%.)
//
// Prologue: build this block's 64-patch keep bitmap directly from
// mask_indices (fused; no builder kernel, no global mask array):
//   - each thread reads 8 of this image's 3072 indices (coalesced,
//     L2-resident), range-tests against this patch-row, atomicOr into
//     2 shared words (~48/3072 hits -> near-zero contention).
//
// Main: a patch spans 8 consecutive rows sharing one mask bit. Each thread
// owns one float4 column across the 8 rows of its patch band:
//   - keep: 8x LDG.128 front-batched (MLP=8) + 8x STG.128
//   - drop: 8x STG.128 of zeros, image never read (75% read elision)
// Consecutive threads -> consecutive float4s within a row: fully coalesced.
// Row stride = 384 float4 = 6144 B. .cs hints: zero-reuse stream.
//
// Tuning history (isolated probes off this base, ALL regressed or tied):
//   R5  occupancy up (chunked loads, regs 30)     -> 44.9 us, DRAM 66%
//   R6  2 bands sequential per thread             -> 45.0 us, DRAM 66%
//   R7  MLP 16 (2 cols/thread, 192 thr)           -> 44.5 us, DRAM 66%
//   R8  default store policy (no .cs)             -> 43.6 us (tie)
//   R9  persistent 592 blocks                     -> 49.6 us, DRAM 60%
//   R10 256-bit v8.f32 ops                        -> 45.3 us, DRAM 64%
//   R12 2 bands concurrent (768 thr)              -> 45.6 us, DRAM 65%
//   R14 transposed grid order                     -> 54.2 us, DRAM 55%
//   R16 convergent store path                     -> 44.0 us (tie)
// Residual gap to HBM spec is read/write turnaround on an 80%-write
// mixed stream; no SM-side lever moved it.
__global__ void __launch_bounds__(384)
random_mask_kernel(const float4* __restrict__ img,
                   const int*    __restrict__ mask_indices,
                   float4*       __restrict__ out) {
    const int pr = blockIdx.x;            // patch row   [0, 64)
    const int b  = blockIdx.y;            // image       [0, 64)
    const int t  = threadIdx.x;           // float4 col  [0, 384)

    // ---- build 64-bit masked-bitmap for this (image, patch-row) ----
    __shared__ uint32_t masked_bits[2];
    if (t < 2) masked_bits[t] = 0;
    __syncthreads();

    const int* mi = mask_indices + b * NUM_MASK;
    const int lo = pr << 6;               // first patch id of this row
#pragma unroll
    for (int j = 0; j < 8; j++) {
        int idx = mi[t + j * 384];        // coalesced, L2-resident
        unsigned d = (unsigned)(idx - lo);
        if (d < 64u) atomicOr(&masked_bits[d >> 5], 1u << (d & 31));
    }
    __syncthreads();

    const int p = t / 6;                  // patch col: 6 float4 per patch
    const bool keep = !((masked_bits[p >> 5] >> (p & 31)) & 1u);

    // ---- stream the 8-row band ----
    const long base = ((long)(b * NH + (pr << 3)) * 384) + t;
    const float4* ip = img + base;
    float4*       op = out + base;

    if (keep) {
        float4 v[8];
#pragma unroll
        for (int r = 0; r < 8; r++) v[r] = __ldcs(ip + r * 384);
#pragma unroll
        for (int r = 0; r < 8; r++) __stcs(op + r * 384, v[r]);
    } else {
        const float4 z = make_float4(0.f, 0.f, 0.f, 0.f);
#pragma unroll
        for (int r = 0; r < 8; r++) __stcs(op + r * 384, z);
    }
}

// ---------------------------------------------------------------------------
extern "C" void kernel_launch(void* const* d_in, const int* in_sizes, int n_in,
                              void* d_out, int out_size) {
    const float4* img = (const float4*)d_in[0];       // images [64,512,512,3] f32
    const int* mask_indices = (const int*)d_in[1];    // [64, 3072] i32
    float4* out = (float4*)d_out;

    dim3 grid(64, NB);                    // (patch-rows, images)
    random_mask_kernel<<<grid, 384>>>(img, mask_indices, out);
}